// round 1
// baseline (speedup 1.0000x reference)
#include <cuda_runtime.h>
#include <cuda_bf16.h>

#define BB 4
#define PP 512
#define KK 4
#define HH 200
#define WW 336
#define AA 14
#define PS 56
#define SCALE 0.25f

__global__ __launch_bounds__(256, 8)
void Blender_38809324486930_kernel(const float* __restrict__ bases,
                                   const float* __restrict__ boxes,
                                   const float* __restrict__ attn,
                                   float* __restrict__ out)
{
    const int bp = blockIdx.x;           // 0 .. B*P-1
    const int b  = bp >> 9;              // P = 512
    // const int p = bp & 511;

    __shared__ float s_attn[KK * AA * AA];   // 784 floats = 3.1 KB
    __shared__ float s_box[4];

    const float* ap = attn + (size_t)bp * (KK * AA * AA);
    for (int i = threadIdx.x; i < KK * AA * AA; i += blockDim.x)
        s_attn[i] = ap[i];
    if (threadIdx.x < 4)
        s_box[threadIdx.x] = boxes[bp * 4 + threadIdx.x];
    __syncthreads();

    // RoI parameters (match reference op order exactly)
    const float x1 = s_box[0] * SCALE;
    const float y1 = s_box[1] * SCALE;
    const float rw = fmaxf(s_box[2] * SCALE - x1, 1.0f);
    const float rh = fmaxf(s_box[3] * SCALE - y1, 1.0f);
    const float bw = rw * (1.0f / PS);
    const float bh = rh * (1.0f / PS);

    const float* fb = bases + (size_t)b * (KK * HH * WW);
    float* ob = out + (size_t)bp * (PS * PS);

    const float resize_step = (float)(AA - 1) / (float)(PS - 1);  // 13/55 in f32

    for (int idx = threadIdx.x; idx < PS * PS; idx += blockDim.x) {
        const int oy = idx / PS;
        const int ox = idx - oy * PS;

        // ---- RoIAlign sample (sampling_ratio = 1 -> bin center) ----
        const float sx = x1 + ((float)ox + 0.5f) * bw;
        const float sy = y1 + ((float)oy + 0.5f) * bh;
        const bool valid = (sy > -1.0f) && (sy < (float)HH) &&
                           (sx > -1.0f) && (sx < (float)WW);
        const float yc = fminf(fmaxf(sy, 0.0f), (float)(HH - 1));
        const float xc = fminf(fmaxf(sx, 0.0f), (float)(WW - 1));
        const int y0 = (int)floorf(yc);
        const int x0 = (int)floorf(xc);
        const int y1i = min(y0 + 1, HH - 1);
        const int x1i = min(x0 + 1, WW - 1);
        const float ly = yc - (float)y0;
        const float lx = xc - (float)x0;
        const float w00 = (1.0f - ly) * (1.0f - lx);
        const float w01 = (1.0f - ly) * lx;
        const float w10 = ly * (1.0f - lx);
        const float w11 = ly * lx;
        const int i00 = y0 * WW + x0;
        const int i01 = y0 * WW + x1i;
        const int i10 = y1i * WW + x0;
        const int i11 = y1i * WW + x1i;
        const float vmask = valid ? 1.0f : 0.0f;

        // ---- attention bilinear resize (align_corners=True) ----
        const float srcx = (float)ox * resize_step;
        const float srcy = (float)oy * resize_step;
        int ax0 = (int)floorf(srcx); ax0 = min(max(ax0, 0), AA - 2);
        int ay0 = (int)floorf(srcy); ay0 = min(max(ay0, 0), AA - 2);
        const float tx = srcx - (float)ax0;
        const float ty = srcy - (float)ay0;
        const float a00 = (1.0f - ty) * (1.0f - tx);
        const float a01 = (1.0f - ty) * tx;
        const float a10 = ty * (1.0f - tx);
        const float a11 = ty * tx;
        const int ai0 = ay0 * AA + ax0;
        const int ai1 = (ay0 + 1) * AA + ax0;

        float attv[KK];
        float roiv[KK];
        float m = -3.402823466e+38f;
        #pragma unroll
        for (int k = 0; k < KK; k++) {
            const float* f = fb + k * (HH * WW);
            const float r = (f[i00] * w00 + f[i01] * w01 +
                             f[i10] * w10 + f[i11] * w11) * vmask;
            roiv[k] = r;
            const float* sa = s_attn + k * (AA * AA);
            const float av = sa[ai0] * a00 + sa[ai0 + 1] * a01 +
                             sa[ai1] * a10 + sa[ai1 + 1] * a11;
            attv[k] = av;
            m = fmaxf(m, av);
        }

        float se = 0.0f;
        float acc = 0.0f;
        #pragma unroll
        for (int k = 0; k < KK; k++) {
            const float e = expf(attv[k] - m);
            se += e;
            acc += e * roiv[k];
        }
        ob[idx] = acc / se;
    }
}

extern "C" void kernel_launch(void* const* d_in, const int* in_sizes, int n_in,
                              void* d_out, int out_size)
{
    const float* bases = (const float*)d_in[0];
    const float* boxes = (const float*)d_in[1];
    const float* attn  = (const float*)d_in[2];
    float* out = (float*)d_out;

    dim3 grid(BB * PP);
    dim3 block(256);
    Blender_38809324486930_kernel<<<grid, block>>>(bases, boxes, attn, out);
}

// round 2
// speedup vs baseline: 1.1884x; 1.1884x over previous
#include <cuda_runtime.h>
#include <cuda_bf16.h>

#define BB 4
#define PP 512
#define KK 4
#define HH 200
#define WW 336
#define AA 14
#define PS 56
#define SCALE 0.25f

// bases transposed to [B][H][W][K] as float4 (K innermost)
__device__ float4 g_basesT[BB * HH * WW];

__global__ __launch_bounds__(256)
void transpose_bases_kernel(const float* __restrict__ bases)
{
    int i = blockIdx.x * blockDim.x + threadIdx.x;   // over B*H*W
    if (i >= BB * HH * WW) return;
    int b  = i / (HH * WW);
    int yx = i - b * (HH * WW);
    const float* p = bases + (size_t)b * (KK * HH * WW) + yx;
    g_basesT[i] = make_float4(p[0], p[HH * WW], p[2 * HH * WW], p[3 * HH * WW]);
}

__global__ __launch_bounds__(256, 8)
void Blender_38809324486930_kernel(const float* __restrict__ boxes,
                                   const float* __restrict__ attn,
                                   float* __restrict__ out)
{
    const int bp = blockIdx.x;           // 0 .. B*P-1
    const int b  = bp >> 9;              // P = 512

    // shared
    __shared__ float s_attnT[AA * AA * KK];      // [ay][ax][k]  3136 B
    __shared__ float s_rowv[PS * AA * KK];       // [oy][j][k]  12544 B
    __shared__ int   s_x0[PS], s_x1[PS];         // feat x taps (float4 units)
    __shared__ float s_lx[PS], s_vx[PS];
    __shared__ int   s_y0[PS], s_y1[PS];         // pre-multiplied by WW
    __shared__ float s_ly[PS], s_vy[PS];
    __shared__ int   s_axi[PS];                  // ax0*4 offset into rowv row
    __shared__ float s_axt[PS];
    __shared__ int   s_ay0[PS];
    __shared__ float s_ayt[PS];

    const int tid = threadIdx.x;

    // ---- load attention tile transposed to [ay][ax][k] ----
    {
        const float* ap = attn + (size_t)bp * (KK * AA * AA);
        for (int i = tid; i < KK * AA * AA; i += 256) {
            int k  = i / (AA * AA);
            int yx = i - k * (AA * AA);
            s_attnT[yx * KK + k] = ap[i];
        }
    }

    // ---- coordinate LUTs ----
    const float resize_step = (float)(AA - 1) / (float)(PS - 1);
    if (tid < PS) {
        const int ox = tid;
        const float bx1 = __ldg(&boxes[bp * 4 + 0]) * SCALE;
        const float bx2 = __ldg(&boxes[bp * 4 + 2]) * SCALE;
        const float bw = fmaxf(bx2 - bx1, 1.0f) * (1.0f / PS);
        const float sx = bx1 + ((float)ox + 0.5f) * bw;
        const float vx = (sx > -1.0f && sx < (float)WW) ? 1.0f : 0.0f;
        const float xc = fminf(fmaxf(sx, 0.0f), (float)(WW - 1));
        const int x0 = (int)floorf(xc);
        s_x0[ox] = x0;
        s_x1[ox] = min(x0 + 1, WW - 1);
        s_lx[ox] = xc - (float)x0;
        s_vx[ox] = vx;

        const float srcx = (float)ox * resize_step;
        int ax0 = (int)floorf(srcx);
        ax0 = min(max(ax0, 0), AA - 2);
        s_axi[ox] = ax0 * KK;
        s_axt[ox] = srcx - (float)ax0;
    } else if (tid >= 64 && tid < 64 + PS) {
        const int oy = tid - 64;
        const float by1 = __ldg(&boxes[bp * 4 + 1]) * SCALE;
        const float by2 = __ldg(&boxes[bp * 4 + 3]) * SCALE;
        const float bh = fmaxf(by2 - by1, 1.0f) * (1.0f / PS);
        const float sy = by1 + ((float)oy + 0.5f) * bh;
        const float vy = (sy > -1.0f && sy < (float)HH) ? 1.0f : 0.0f;
        const float yc = fminf(fmaxf(sy, 0.0f), (float)(HH - 1));
        const int y0 = (int)floorf(yc);
        s_y0[oy] = y0 * WW;
        s_y1[oy] = min(y0 + 1, HH - 1) * WW;
        s_ly[oy] = yc - (float)y0;
        s_vy[oy] = vy;

        const float srcy = (float)oy * resize_step;
        int ay0 = (int)floorf(srcy);
        ay0 = min(max(ay0, 0), AA - 2);
        s_ay0[oy] = ay0;
        s_ayt[oy] = srcy - (float)ay0;
    }
    __syncthreads();

    // ---- precompute row-interpolated attention: rowv[oy][j][k] ----
    for (int e = tid; e < PS * AA; e += 256) {
        const int oy = e / AA;
        const int j  = e - oy * AA;
        const int ay0 = s_ay0[oy];
        const float ty = s_ayt[oy];
        const float4 a0 = *(const float4*)&s_attnT[(ay0 * AA + j) * KK];
        const float4 a1 = *(const float4*)&s_attnT[((ay0 + 1) * AA + j) * KK];
        float4 r;
        r.x = a0.x + ty * (a1.x - a0.x);
        r.y = a0.y + ty * (a1.y - a0.y);
        r.z = a0.z + ty * (a1.z - a0.z);
        r.w = a0.w + ty * (a1.w - a0.w);
        *(float4*)&s_rowv[e * KK] = r;
    }
    __syncthreads();

    const float4* fb = g_basesT + (size_t)b * (HH * WW);
    float* ob = out + (size_t)bp * (PS * PS);

    for (int idx = tid; idx < PS * PS; idx += 256) {
        const int oy = idx / PS;
        const int ox = idx - oy * PS;

        // ---- RoIAlign: one float4 per tap ----
        const int y0o = s_y0[oy], y1o = s_y1[oy];
        const int x0 = s_x0[ox], x1 = s_x1[ox];
        const float ly = s_ly[oy], lx = s_lx[ox];
        const float vmask = s_vy[oy] * s_vx[ox];
        const float w11 = ly * lx;
        const float w10 = ly - w11;
        const float w01 = lx - w11;
        const float w00 = 1.0f - ly - lx + w11;

        const float4 f00 = __ldg(&fb[y0o + x0]);
        const float4 f01 = __ldg(&fb[y0o + x1]);
        const float4 f10 = __ldg(&fb[y1o + x0]);
        const float4 f11 = __ldg(&fb[y1o + x1]);

        float4 r;
        r.x = (f00.x * w00 + f01.x * w01 + f10.x * w10 + f11.x * w11) * vmask;
        r.y = (f00.y * w00 + f01.y * w01 + f10.y * w10 + f11.y * w11) * vmask;
        r.z = (f00.z * w00 + f01.z * w01 + f10.z * w10 + f11.z * w11) * vmask;
        r.w = (f00.w * w00 + f01.w * w01 + f10.w * w10 + f11.w * w11) * vmask;

        // ---- attention column lerp ----
        const int rb = oy * (AA * KK) + s_axi[ox];
        const float tx = s_axt[ox];
        const float4 a0 = *(const float4*)&s_rowv[rb];
        const float4 a1 = *(const float4*)&s_rowv[rb + KK];
        float4 a;
        a.x = a0.x + tx * (a1.x - a0.x);
        a.y = a0.y + tx * (a1.y - a0.y);
        a.z = a0.z + tx * (a1.z - a0.z);
        a.w = a0.w + tx * (a1.w - a0.w);

        // ---- softmax-blend (pivot on a.x; 3 exps) ----
        const float e1 = __expf(a.y - a.x);
        const float e2 = __expf(a.z - a.x);
        const float e3 = __expf(a.w - a.x);
        const float se  = 1.0f + e1 + e2 + e3;
        const float acc = r.x + e1 * r.y + e2 * r.z + e3 * r.w;
        ob[idx] = __fdividef(acc, se);
    }
}

extern "C" void kernel_launch(void* const* d_in, const int* in_sizes, int n_in,
                              void* d_out, int out_size)
{
    const float* bases = (const float*)d_in[0];
    const float* boxes = (const float*)d_in[1];
    const float* attn  = (const float*)d_in[2];
    float* out = (float*)d_out;

    const int nT = BB * HH * WW;
    transpose_bases_kernel<<<(nT + 255) / 256, 256>>>(bases);
    Blender_38809324486930_kernel<<<BB * PP, 256>>>(boxes, attn, out);
}

// round 3
// speedup vs baseline: 1.3827x; 1.1635x over previous
#include <cuda_runtime.h>
#include <cuda_bf16.h>

#define BB 4
#define PP 512
#define KK 4
#define HH 200
#define WW 336
#define AA 14
#define PS 56
#define SCALE 0.25f
#define NTHREADS 224   /* 4 rows x 56 cols */
#define NROWITER 14    /* 56 / 4 */

// bases transposed to [B][H][W][K] as float4 (K innermost)
__device__ float4 g_basesT[BB * HH * WW];

__global__ __launch_bounds__(256)
void transpose_bases_kernel(const float* __restrict__ bases)
{
    int i = blockIdx.x * blockDim.x + threadIdx.x;   // over B*H*W
    if (i >= BB * HH * WW) return;
    int b  = i / (HH * WW);
    int yx = i - b * (HH * WW);
    const float* p = bases + (size_t)b * (KK * HH * WW) + yx;
    g_basesT[i] = make_float4(p[0], p[HH * WW], p[2 * HH * WW], p[3 * HH * WW]);
}

__global__ __launch_bounds__(NTHREADS, 8)
void Blender_38809324486930_kernel(const float* __restrict__ boxes,
                                   const float* __restrict__ attn,
                                   float* __restrict__ out)
{
    const int bp = blockIdx.x;           // 0 .. B*P-1
    const int b  = bp >> 9;              // P = 512

    __shared__ float s_attnT[AA * AA * KK];      // [ay][ax][k]
    __shared__ float s_rowv[PS * AA * KK];       // [oy][j][k]

    const int tid = threadIdx.x;
    const int ox  = tid % PS;            // fixed column per thread
    const int r0  = tid / PS;            // starting row (0..3)

    // ---- load attention tile transposed to [ay][ax][k] ----
    {
        const float* ap = attn + (size_t)bp * (KK * AA * AA);
        for (int i = tid; i < KK * AA * AA; i += NTHREADS) {
            int k  = i / (AA * AA);
            int yx = i - k * (AA * AA);
            s_attnT[yx * KK + k] = ap[i];
        }
    }

    // ---- box (broadcast loads) ----
    const float bx1 = __ldg(&boxes[bp * 4 + 0]) * SCALE;
    const float by1 = __ldg(&boxes[bp * 4 + 1]) * SCALE;
    const float bx2 = __ldg(&boxes[bp * 4 + 2]) * SCALE;
    const float by2 = __ldg(&boxes[bp * 4 + 3]) * SCALE;
    const float bw = fmaxf(bx2 - bx1, 1.0f) * (1.0f / PS);
    const float bh = fmaxf(by2 - by1, 1.0f) * (1.0f / PS);

    const float resize_step = (float)(AA - 1) / (float)(PS - 1);

    // ---- per-thread x state (registers, computed once) ----
    const float sx = bx1 + ((float)ox + 0.5f) * bw;
    const float vx = (sx > -1.0f && sx < (float)WW) ? 1.0f : 0.0f;
    const float xc = fminf(fmaxf(sx, 0.0f), (float)(WW - 1));
    const int   x0 = (int)floorf(xc);
    const int   x1 = min(x0 + 1, WW - 1);
    const float lx = xc - (float)x0;

    const float srcx = (float)ox * resize_step;
    int ax0 = min(max((int)floorf(srcx), 0), AA - 2);
    const float tx = srcx - (float)ax0;
    const int axk = ax0 * KK;

    __syncthreads();

    // ---- precompute row-interpolated attention: rowv[oy][j][k] ----
    for (int e = tid; e < PS * AA; e += NTHREADS) {
        const int oy = e / AA;
        const int j  = e - oy * AA;
        const float srcy = (float)oy * resize_step;
        const int ay0 = min(max((int)floorf(srcy), 0), AA - 2);
        const float ty = srcy - (float)ay0;
        const float4 a0 = *(const float4*)&s_attnT[(ay0 * AA + j) * KK];
        const float4 a1 = *(const float4*)&s_attnT[((ay0 + 1) * AA + j) * KK];
        float4 rr;
        rr.x = a0.x + ty * (a1.x - a0.x);
        rr.y = a0.y + ty * (a1.y - a0.y);
        rr.z = a0.z + ty * (a1.z - a0.z);
        rr.w = a0.w + ty * (a1.w - a0.w);
        *(float4*)&s_rowv[e * KK] = rr;
    }
    __syncthreads();

    const float4* fb = g_basesT + (size_t)b * (HH * WW);
    float* ob = out + (size_t)bp * (PS * PS) + tid;

    #pragma unroll 2
    for (int it = 0; it < NROWITER; it++) {
        const int oy = r0 + it * 4;

        // ---- per-row y state (registers) ----
        const float sy = by1 + ((float)oy + 0.5f) * bh;
        const float vy = (sy > -1.0f && sy < (float)HH) ? 1.0f : 0.0f;
        const float yc = fminf(fmaxf(sy, 0.0f), (float)(HH - 1));
        const int   y0 = (int)floorf(yc);
        const float ly = yc - (float)y0;
        const int y0o = y0 * WW;
        const int y1o = min(y0 + 1, HH - 1) * WW;

        const float vmask = vy * vx;
        const float w11 = ly * lx;
        const float w10 = ly - w11;
        const float w01 = lx - w11;
        const float w00 = 1.0f - ly - lx + w11;

        // ---- RoIAlign: one float4 per tap ----
        const float4 f00 = __ldg(&fb[y0o + x0]);
        const float4 f01 = __ldg(&fb[y0o + x1]);
        const float4 f10 = __ldg(&fb[y1o + x0]);
        const float4 f11 = __ldg(&fb[y1o + x1]);

        float4 rv;
        rv.x = (f00.x * w00 + f01.x * w01 + f10.x * w10 + f11.x * w11) * vmask;
        rv.y = (f00.y * w00 + f01.y * w01 + f10.y * w10 + f11.y * w11) * vmask;
        rv.z = (f00.z * w00 + f01.z * w01 + f10.z * w10 + f11.z * w11) * vmask;
        rv.w = (f00.w * w00 + f01.w * w01 + f10.w * w10 + f11.w * w11) * vmask;

        // ---- attention column lerp ----
        const int rb = oy * (AA * KK) + axk;
        const float4 a0 = *(const float4*)&s_rowv[rb];
        const float4 a1 = *(const float4*)&s_rowv[rb + KK];
        float4 a;
        a.x = a0.x + tx * (a1.x - a0.x);
        a.y = a0.y + tx * (a1.y - a0.y);
        a.z = a0.z + tx * (a1.z - a0.z);
        a.w = a0.w + tx * (a1.w - a0.w);

        // ---- softmax-blend (pivot on a.x; 3 exps) ----
        const float e1 = __expf(a.y - a.x);
        const float e2 = __expf(a.z - a.x);
        const float e3 = __expf(a.w - a.x);
        const float se  = 1.0f + e1 + e2 + e3;
        const float acc = rv.x + e1 * rv.y + e2 * rv.z + e3 * rv.w;
        ob[it * NTHREADS] = __fdividef(acc, se);
    }
}

extern "C" void kernel_launch(void* const* d_in, const int* in_sizes, int n_in,
                              void* d_out, int out_size)
{
    const float* bases = (const float*)d_in[0];
    const float* boxes = (const float*)d_in[1];
    const float* attn  = (const float*)d_in[2];
    float* out = (float*)d_out;

    const int nT = BB * HH * WW;
    transpose_bases_kernel<<<(nT + 255) / 256, 256>>>(bases);
    Blender_38809324486930_kernel<<<BB * PP, NTHREADS>>>(boxes, attn, out);
}